// round 2
// baseline (speedup 1.0000x reference)
#include <cuda_runtime.h>
#include <cstdint>

#define Bn 4
#define Cn 64
#define Nn 16384
#define On 128
#define Kn 16
#define EPSf 1e-5f
#define NEGf 0.2f

#define QT 128          // queries per KNN block (1 thread = 1 query)
#define CT 128          // candidate tile
#define PTS 32          // points per edge block

// -------- scratch (__device__ globals: no allocation allowed) --------
__device__ __align__(16) float g_xt[Bn * Nn * Cn];   // (b, n, c)  16 MB
__device__ float g_xn[Bn * Nn];                      // squared norms
__device__ __align__(16) int   g_idx[Bn * Nn * Kn];  // knn indices
__device__ __align__(16) float g_w1[Cn * On];        // w1[c][o] = W[o][c]
__device__ __align__(16) float g_wd[Cn * On];        // wd[c][o] = W[o][64+c]-W[o][c]
__device__ float g_scale[On];
__device__ float g_bias[On];

// ---------------- weight / BN prep ----------------
__global__ void prep_kernel(const float* __restrict__ W,
                            const float* __restrict__ gamma,
                            const float* __restrict__ beta,
                            const float* __restrict__ bn_mean,
                            const float* __restrict__ bn_var) {
    int o = threadIdx.x;  // 0..127
    float sc = gamma[o] * rsqrtf(bn_var[o] + EPSf);
    g_scale[o] = sc;
    g_bias[o]  = beta[o] - bn_mean[o] * sc;
    for (int c = 0; c < Cn; c++) {
        float w1 = W[o * (2 * Cn) + c];
        float w2 = W[o * (2 * Cn) + Cn + c];
        g_w1[c * On + o] = w1;
        g_wd[c * On + o] = w2 - w1;
    }
}

// ---------------- transpose x (B,C,N) -> xt (B,N,C) ----------------
__global__ void transpose_kernel(const float* __restrict__ x) {
    __shared__ float s[32][65];
    int b  = blockIdx.y;
    int nb = blockIdx.x * 32;
    int tx = threadIdx.x;   // 0..31 (n)
    int ty = threadIdx.y;   // 0..7
    const float* xb = x + (size_t)b * Cn * Nn;
#pragma unroll
    for (int i = 0; i < 8; i++) {
        int c = ty * 8 + i;
        s[tx][c] = xb[(size_t)c * Nn + nb + tx];
    }
    __syncthreads();
    int t = ty * 32 + tx;           // 0..255
    int r = t >> 3;                 // row 0..31
    int c0 = (t & 7) * 8;           // col group
    float* dst = g_xt + ((size_t)b * Nn + nb + r) * Cn + c0;
#pragma unroll
    for (int i = 0; i < 8; i++) dst[i] = s[r][c0 + i];
}

// ---------------- squared norms (coalesced over n) ----------------
__global__ void norm_kernel(const float* __restrict__ x) {
    int n = blockIdx.x * blockDim.x + threadIdx.x;
    int b = blockIdx.y;
    const float* xb = x + (size_t)b * Cn * Nn + n;
    float s = 0.f;
#pragma unroll
    for (int c = 0; c < Cn; c++) { float v = xb[(size_t)c * Nn]; s += v * v; }
    g_xn[b * Nn + n] = s;
}

// ---------------- KNN: 1 thread = 1 query, top-16 of (2*q.x_j - |x_j|^2) ----------------
__global__ __launch_bounds__(QT, 4) void knn_kernel() {
    __shared__ __align__(16) float cand_s[CT * Cn];   // 32 KB
    __shared__ float norm_s[CT];

    const int blocks_per_batch = Nn / QT;
    int b  = blockIdx.x / blocks_per_batch;
    int qi = (blockIdx.x % blocks_per_batch) * QT + threadIdx.x;

    const float* xtb = g_xt + (size_t)b * Nn * Cn;
    const float* xnb = g_xn + (size_t)b * Nn;

    float q[Cn];
    {
        const float4* qp = (const float4*)(xtb + (size_t)qi * Cn);
#pragma unroll
        for (int i = 0; i < Cn / 4; i++) {
            float4 v = qp[i];
            q[4*i+0] = 2.f * v.x; q[4*i+1] = 2.f * v.y;
            q[4*i+2] = 2.f * v.z; q[4*i+3] = 2.f * v.w;
        }
    }

    float vtop[Kn];
    int   itop[Kn];
#pragma unroll
    for (int t = 0; t < Kn; t++) { vtop[t] = -3.402823466e38f; itop[t] = 0; }
    float vmin = -3.402823466e38f;
    int   smin = 0;

    for (int tile = 0; tile < Nn / CT; tile++) {
        // cooperative tile load
        const float4* src = (const float4*)(xtb + (size_t)tile * CT * Cn);
        float4* dst = (float4*)cand_s;
#pragma unroll
        for (int i = 0; i < (CT * Cn / 4) / QT; i++)
            dst[threadIdx.x + i * QT] = src[threadIdx.x + i * QT];
        norm_s[threadIdx.x] = xnb[tile * CT + threadIdx.x];
        __syncthreads();

        int jg0 = tile * CT;
        for (int j = 0; j < CT; j++) {
            const float4* cp = (const float4*)(cand_s + j * Cn);
            float d0 = 0.f, d1 = 0.f, d2 = 0.f, d3 = 0.f;
#pragma unroll
            for (int i = 0; i < Cn / 4; i++) {
                float4 cv = cp[i];
                d0 += q[4*i+0] * cv.x;
                d1 += q[4*i+1] * cv.y;
                d2 += q[4*i+2] * cv.z;
                d3 += q[4*i+3] * cv.w;
            }
            float s = (d0 + d1) + (d2 + d3) - norm_s[j];
            int jg = jg0 + j;
            if (s > vmin && jg != qi) {
                vtop[smin] = s; itop[smin] = jg;
                vmin = vtop[0]; smin = 0;
#pragma unroll
                for (int t = 1; t < Kn; t++)
                    if (vtop[t] < vmin) { vmin = vtop[t]; smin = t; }
            }
        }
        __syncthreads();
    }

    int* op = g_idx + ((size_t)b * Nn + qi) * Kn;
#pragma unroll
    for (int t = 0; t < Kn; t++) op[t] = itop[t];
}

// ---------------- edge conv + BN + lrelu + max over k ----------------
// smem: w1[64][128] | feat 8 warps x 17 rows x 64 | outs[32][132] | scale/bias
#define EDGE_SMEM_FLOATS (Cn*On + 8*17*Cn + PTS*132 + 2*On)

__global__ __launch_bounds__(256, 2) void edge_kernel(float* __restrict__ out) {
    extern __shared__ float sm[];
    float* w1   = sm;                       // 8192
    float* feat = w1 + Cn * On;             // 8704
    float* outs = feat + 8 * 17 * Cn;       // 32*132 = 4224
    float* ssc  = outs + PTS * 132;         // 128
    float* sbi  = ssc + On;                 // 128

    int tid = threadIdx.x, wid = tid >> 5, lane = tid & 31;

    for (int i = tid; i < Cn * On; i += 256) w1[i] = g_w1[i];
    if (tid < On) { ssc[tid] = g_scale[tid]; sbi[tid] = g_bias[tid]; }
    __syncthreads();

    int gp    = blockIdx.x * PTS;
    int b     = gp / Nn;
    int nbase = gp % Nn;
    const float* xtb = g_xt + (size_t)b * Nn * Cn;
    float* fw = feat + wid * 17 * Cn;
    int o0 = lane << 2;

#pragma unroll 1
    for (int pp = 0; pp < PTS / 8; pp++) {
        int pt = pp * 8 + wid;
        int n  = nbase + pt;

        // gather 16 neighbor rows + center (row 16), 2 rows per iteration
        const int* ip = g_idx + ((size_t)b * Nn + n) * Kn;
        int myid = (lane < Kn) ? ip[lane] : n;
#pragma unroll
        for (int r = 0; r < 18; r += 2) {
            int rr = r + (lane >> 4);
            int rowid = __shfl_sync(0xffffffffu, myid, rr & 31);
            if (rr >= Kn) rowid = n;
            if (rr < 17)
                ((float4*)(fw + rr * Cn))[lane & 15] =
                    ((const float4*)(xtb + (size_t)rowid * Cn))[lane & 15];
        }
        __syncwarp();

        // per-point constant: (W2 - W1) @ center
        float csv[4] = {0.f, 0.f, 0.f, 0.f};
        {
            const float* cen = fw + 16 * Cn;
#pragma unroll
            for (int c = 0; c < Cn; c++) {
                float e = cen[c];
                float4 wv = *(const float4*)(g_wd + c * On + o0);
                csv[0] += wv.x * e; csv[1] += wv.y * e;
                csv[2] += wv.z * e; csv[3] += wv.w * e;
            }
        }

        // GEMV per neighbor, running max/min of raw scores
        float mx[4], mn[4];
#pragma unroll 1
        for (int k = 0; k < Kn; k++) {
            const float4* fr = (const float4*)(fw + k * Cn);
            float a0 = 0.f, a1 = 0.f, a2 = 0.f, a3 = 0.f;
#pragma unroll
            for (int c4 = 0; c4 < Cn / 4; c4++) {
                float4 e = fr[c4];
                const float* wb = w1 + (c4 * 4) * On + o0;
                float4 w0 = *(const float4*)(wb);
                a0 += w0.x * e.x; a1 += w0.y * e.x; a2 += w0.z * e.x; a3 += w0.w * e.x;
                float4 wv1 = *(const float4*)(wb + On);
                a0 += wv1.x * e.y; a1 += wv1.y * e.y; a2 += wv1.z * e.y; a3 += wv1.w * e.y;
                float4 wv2 = *(const float4*)(wb + 2 * On);
                a0 += wv2.x * e.z; a1 += wv2.y * e.z; a2 += wv2.z * e.z; a3 += wv2.w * e.z;
                float4 wv3 = *(const float4*)(wb + 3 * On);
                a0 += wv3.x * e.w; a1 += wv3.y * e.w; a2 += wv3.z * e.w; a3 += wv3.w * e.w;
            }
            if (k == 0) {
                mx[0] = a0; mx[1] = a1; mx[2] = a2; mx[3] = a3;
                mn[0] = a0; mn[1] = a1; mn[2] = a2; mn[3] = a3;
            } else {
                mx[0] = fmaxf(mx[0], a0); mn[0] = fminf(mn[0], a0);
                mx[1] = fmaxf(mx[1], a1); mn[1] = fminf(mn[1], a1);
                mx[2] = fmaxf(mx[2], a2); mn[2] = fminf(mn[2], a2);
                mx[3] = fmaxf(mx[3], a3); mn[3] = fminf(mn[3], a3);
            }
        }

        // BN + lrelu via monotonicity, stash in outs[pt][o]
        float* od = outs + pt * 132 + o0;
#pragma unroll
        for (int r = 0; r < 4; r++) {
            float sc = ssc[o0 + r];
            float bi = sbi[o0 + r];
            float base = (sc > 0.f ? mx[r] : mn[r]) + csv[r];
            float yv = fmaf(sc, base, bi);
            yv = yv > 0.f ? yv : NEGf * yv;
            od[r] = yv;
        }
        __syncwarp();
    }

    __syncthreads();
    // coalesced write: out (B, O, N)
    {
        int o = tid >> 1, h = tid & 1;
        float* dst = out + ((size_t)(b * On + o)) * Nn + nbase + h * 16;
#pragma unroll
        for (int i4 = 0; i4 < 4; i4++) {
            float4 vv;
            vv.x = outs[(h * 16 + i4 * 4 + 0) * 132 + o];
            vv.y = outs[(h * 16 + i4 * 4 + 1) * 132 + o];
            vv.z = outs[(h * 16 + i4 * 4 + 2) * 132 + o];
            vv.w = outs[(h * 16 + i4 * 4 + 3) * 132 + o];
            *(float4*)(dst + i4 * 4) = vv;
        }
    }
}

// ---------------- launch ----------------
extern "C" void kernel_launch(void* const* d_in, const int* in_sizes, int n_in,
                              void* d_out, int out_size) {
    const float* x       = (const float*)d_in[0];
    const float* W       = (const float*)d_in[1];
    const float* gamma   = (const float*)d_in[2];
    const float* beta    = (const float*)d_in[3];
    const float* bn_mean = (const float*)d_in[4];
    const float* bn_var  = (const float*)d_in[5];
    float* out = (float*)d_out;

    const size_t edge_smem = EDGE_SMEM_FLOATS * sizeof(float);
    cudaFuncSetAttribute(edge_kernel, cudaFuncAttributeMaxDynamicSharedMemorySize,
                         (int)edge_smem);

    prep_kernel<<<1, On>>>(W, gamma, beta, bn_mean, bn_var);
    transpose_kernel<<<dim3(Nn / 32, Bn), dim3(32, 8)>>>(x);
    norm_kernel<<<dim3(Nn / 256, Bn), 256>>>(x);
    knn_kernel<<<Bn * (Nn / QT), QT>>>();
    edge_kernel<<<(Bn * Nn) / PTS, 256, edge_smem>>>(out);
}

// round 3
// speedup vs baseline: 1.0030x; 1.0030x over previous
#include <cuda_runtime.h>
#include <cstdint>

#define Bn 4
#define Cn 64
#define Nn 16384
#define On 128
#define Kn 16
#define EPSf 1e-5f
#define NEGf 0.2f
#define FLT_NEG (-3.402823466e38f)

#define QT 128          // queries per KNN block
#define CT 128          // candidates per tile
#define PTS 32          // points per edge block

// -------- scratch (__device__ globals: no allocation allowed) --------
__device__ __align__(16) float g_xt[Bn * Nn * Cn];   // (b, n, c)  16 MB
__device__ float g_xn[Bn * Nn];                      // squared norms
__device__ __align__(16) int   g_idx[Bn * Nn * Kn];  // knn indices
__device__ __align__(16) float g_w1[Cn * On];
__device__ __align__(16) float g_wd[Cn * On];
__device__ float g_scale[On];
__device__ float g_bias[On];

// ---------------- packed f32x2 helpers ----------------
__device__ __forceinline__ void fma2(unsigned long long& d,
                                     unsigned long long a,
                                     unsigned long long b) {
    asm("fma.rn.f32x2 %0, %1, %2, %0;" : "+l"(d) : "l"(a), "l"(b));
}
__device__ __forceinline__ unsigned long long pack2(float v) {
    unsigned long long r;
    asm("mov.b64 %0, {%1, %1};" : "=l"(r) : "f"(v));
    return r;
}
__device__ __forceinline__ void unpack2(unsigned long long v, float& lo, float& hi) {
    asm("mov.b64 {%0, %1}, %2;" : "=f"(lo), "=f"(hi) : "l"(v));
}

// ---------------- weight / BN prep ----------------
__global__ void prep_kernel(const float* __restrict__ W,
                            const float* __restrict__ gamma,
                            const float* __restrict__ beta,
                            const float* __restrict__ bn_mean,
                            const float* __restrict__ bn_var) {
    int o = threadIdx.x;
    float sc = gamma[o] * rsqrtf(bn_var[o] + EPSf);
    g_scale[o] = sc;
    g_bias[o]  = beta[o] - bn_mean[o] * sc;
    for (int c = 0; c < Cn; c++) {
        float w1 = W[o * (2 * Cn) + c];
        float w2 = W[o * (2 * Cn) + Cn + c];
        g_w1[c * On + o] = w1;
        g_wd[c * On + o] = w2 - w1;
    }
}

// ---------------- transpose x (B,C,N) -> xt (B,N,C) ----------------
__global__ void transpose_kernel(const float* __restrict__ x) {
    __shared__ float s[32][65];
    int b  = blockIdx.y;
    int nb = blockIdx.x * 32;
    int tx = threadIdx.x;
    int ty = threadIdx.y;
    const float* xb = x + (size_t)b * Cn * Nn;
#pragma unroll
    for (int i = 0; i < 8; i++) {
        int c = ty * 8 + i;
        s[tx][c] = xb[(size_t)c * Nn + nb + tx];
    }
    __syncthreads();
    int t = ty * 32 + tx;
    int r = t >> 3;
    int c0 = (t & 7) * 8;
    float* dst = g_xt + ((size_t)b * Nn + nb + r) * Cn + c0;
#pragma unroll
    for (int i = 0; i < 8; i++) dst[i] = s[r][c0 + i];
}

// ---------------- squared norms ----------------
__global__ void norm_kernel(const float* __restrict__ x) {
    int n = blockIdx.x * blockDim.x + threadIdx.x;
    int b = blockIdx.y;
    const float* xb = x + (size_t)b * Cn * Nn + n;
    float s = 0.f;
#pragma unroll
    for (int c = 0; c < Cn; c++) { float v = xb[(size_t)c * Nn]; s += v * v; }
    g_xn[b * Nn + n] = s;
}

// ---------------- KNN: tiled 128x128 distance GEMM (f32x2) + selection ----
// smem layout (floats):
//   q_s  [128][68]   queries (x2 prescaled), row-major
//   c_sT [64][132]   candidate tile TRANSPOSED [k][col]
//   S_s  [128][69]   one 64-col phase of scores
//   norm_s[128]
#define QS_STRIDE 68
#define CS_STRIDE 132
#define SS_STRIDE 69
#define KNN_SMEM_FLOATS (128*QS_STRIDE + 64*CS_STRIDE + 128*SS_STRIDE + 128)

__global__ __launch_bounds__(256, 2) void knn_kernel() {
    extern __shared__ float sh[];
    float* q_s    = sh;
    float* c_sT   = q_s + 128 * QS_STRIDE;
    float* S_s    = c_sT + 64 * CS_STRIDE;
    float* norm_s = S_s + 128 * SS_STRIDE;

    const int tid = threadIdx.x;
    const int tx = tid & 15, ty = tid >> 4;
    const int blocks_per_batch = Nn / QT;
    const int b = blockIdx.x / blocks_per_batch;
    const int qbase = (blockIdx.x % blocks_per_batch) * QT;
    const float* xtb = g_xt + (size_t)b * Nn * Cn;
    const float* xnb = g_xn + (size_t)b * Nn;

    // load query tile, fold the 2x into q
#pragma unroll
    for (int it = 0; it < 8; it++) {
        int i = tid + it * 256;               // 0..2047 float4s
        int r = i >> 4, c4 = i & 15;
        float4 v = ((const float4*)(xtb + (size_t)(qbase + r) * Cn))[c4];
        v.x *= 2.f; v.y *= 2.f; v.z *= 2.f; v.w *= 2.f;
        ((float4*)(q_s + r * QS_STRIDE))[c4] = v;
    }

    // per-thread selection state
    float vtop[Kn]; int itop[Kn];
#pragma unroll
    for (int t = 0; t < Kn; t++) { vtop[t] = FLT_NEG; itop[t] = 0; }
    float vmin = FLT_NEG; int smin = 0;
    const int selq = tid & 127;
    const int selhalf = tid >> 7;
    const int qi = qbase + selq;
    const float* Srow = S_s + selq * SS_STRIDE + selhalf * 32;

    for (int tile = 0; tile < Nn / CT; tile++) {
        // ---- load candidate tile TRANSPOSED: c_sT[k][row] ----
#pragma unroll
        for (int it = 0; it < 4; it++) {
            int i = tid + it * 256;           // 0..1023 : 128 rows x 8 col-octets
            int row = i & 127;
            int c8 = i >> 7;                  // 0..7 -> k base 8*c8
            const float4* src = (const float4*)(xtb + (size_t)(tile * CT + row) * Cn + c8 * 8);
            float4 v0 = src[0];
            float4 v1 = src[1];
            float* d = c_sT + (c8 * 8) * CS_STRIDE + row;
            d[0 * CS_STRIDE] = v0.x; d[1 * CS_STRIDE] = v0.y;
            d[2 * CS_STRIDE] = v0.z; d[3 * CS_STRIDE] = v0.w;
            d[4 * CS_STRIDE] = v1.x; d[5 * CS_STRIDE] = v1.y;
            d[6 * CS_STRIDE] = v1.z; d[7 * CS_STRIDE] = v1.w;
        }
        if (tid < 128) norm_s[tid] = xnb[tile * CT + tid];
        __syncthreads();

        // ---- 128x128x64 GEMM, 8x8 per thread, packed f32x2 ----
        unsigned long long acc[8][4];
#pragma unroll
        for (int r = 0; r < 8; r++)
#pragma unroll
            for (int p = 0; p < 4; p++) acc[r][p] = 0ull;

        const float* qbaseptr = q_s + (ty * 8) * QS_STRIDE;
        const float* cb0 = c_sT + 4 * tx;        // cols 4tx..4tx+3
        const float* cb1 = c_sT + 64 + 4 * tx;   // cols 64+4tx..

#pragma unroll 1
        for (int kk = 0; kk < 16; kk++) {
            float4 q4[8];
#pragma unroll
            for (int r = 0; r < 8; r++)
                q4[r] = *(const float4*)(qbaseptr + r * QS_STRIDE + kk * 4);
#pragma unroll
            for (int ks = 0; ks < 4; ks++) {
                int k = kk * 4 + ks;
                unsigned long long cp0 = *(const unsigned long long*)(cb0 + k * CS_STRIDE);
                unsigned long long cp1 = *(const unsigned long long*)(cb0 + k * CS_STRIDE + 2);
                unsigned long long cp2 = *(const unsigned long long*)(cb1 + k * CS_STRIDE);
                unsigned long long cp3 = *(const unsigned long long*)(cb1 + k * CS_STRIDE + 2);
#pragma unroll
                for (int r = 0; r < 8; r++) {
                    float qv = (ks == 0) ? q4[r].x : (ks == 1) ? q4[r].y
                             : (ks == 2) ? q4[r].z : q4[r].w;
                    unsigned long long qq = pack2(qv);
                    fma2(acc[r][0], qq, cp0);
                    fma2(acc[r][1], qq, cp1);
                    fma2(acc[r][2], qq, cp2);
                    fma2(acc[r][3], qq, cp3);
                }
            }
        }

        // ---- two phases of 64 cols: spill scores, then select ----
#pragma unroll
        for (int g = 0; g < 2; g++) {
            float n0 = norm_s[g * 64 + 4 * tx + 0];
            float n1 = norm_s[g * 64 + 4 * tx + 1];
            float n2 = norm_s[g * 64 + 4 * tx + 2];
            float n3 = norm_s[g * 64 + 4 * tx + 3];
#pragma unroll
            for (int r = 0; r < 8; r++) {
                int q = ty * 8 + r;
                float lo0, hi0, lo1, hi1;
                unpack2(acc[r][2 * g + 0], lo0, hi0);
                unpack2(acc[r][2 * g + 1], lo1, hi1);
                float* dst = S_s + q * SS_STRIDE + 4 * tx;
                dst[0] = lo0 - n0;
                dst[1] = hi0 - n1;
                dst[2] = lo1 - n2;
                dst[3] = hi1 - n3;
            }
            __syncthreads();

            // selection: 2 threads per query, 32 cols each
            int jgbase = tile * CT + g * 64 + selhalf * 32;
#pragma unroll 4
            for (int c = 0; c < 32; c++) {
                float sv = Srow[c];
                if (sv > vmin) {
                    int jg = jgbase + c;
                    if (jg != qi) {
                        vtop[smin] = sv; itop[smin] = jg;
                        float m = vtop[0]; int sm = 0;
#pragma unroll
                        for (int t = 1; t < Kn; t++)
                            if (vtop[t] < m) { m = vtop[t]; sm = t; }
                        vmin = m; smin = sm;
                    }
                }
            }
            __syncthreads();
        }
    }

    // ---- merge the two half-scans per query (reuse q_s as buffer) ----
    float* mv = q_s;                      // 128*16 floats
    int*   mi = (int*)(q_s + 128 * 16);
    if (selhalf == 1) {
#pragma unroll
        for (int t = 0; t < Kn; t++) {
            mv[selq * Kn + t] = vtop[t];
            mi[selq * Kn + t] = itop[t];
        }
    }
    __syncthreads();
    if (selhalf == 0) {
#pragma unroll
        for (int t = 0; t < Kn; t++) {
            float sv = mv[selq * Kn + t];
            if (sv > vmin) {
                vtop[smin] = sv; itop[smin] = mi[selq * Kn + t];
                float m = vtop[0]; int sm = 0;
#pragma unroll
                for (int u = 1; u < Kn; u++)
                    if (vtop[u] < m) { m = vtop[u]; sm = u; }
                vmin = m; smin = sm;
            }
        }
        int* op = g_idx + ((size_t)b * Nn + qi) * Kn;
#pragma unroll
        for (int t = 0; t < Kn; t++) op[t] = itop[t];
    }
}

// ---------------- edge conv + BN + lrelu + max over k ----------------
#define EDGE_SMEM_FLOATS (Cn*On + 8*17*Cn + PTS*132 + 2*On)

__global__ __launch_bounds__(256, 2) void edge_kernel(float* __restrict__ out) {
    extern __shared__ float sm[];
    float* w1   = sm;
    float* feat = w1 + Cn * On;
    float* outs = feat + 8 * 17 * Cn;
    float* ssc  = outs + PTS * 132;
    float* sbi  = ssc + On;

    int tid = threadIdx.x, wid = tid >> 5, lane = tid & 31;

    for (int i = tid; i < Cn * On; i += 256) w1[i] = g_w1[i];
    if (tid < On) { ssc[tid] = g_scale[tid]; sbi[tid] = g_bias[tid]; }
    __syncthreads();

    int gp    = blockIdx.x * PTS;
    int b     = gp / Nn;
    int nbase = gp % Nn;
    const float* xtb = g_xt + (size_t)b * Nn * Cn;
    float* fw = feat + wid * 17 * Cn;
    int o0 = lane << 2;

#pragma unroll 1
    for (int pp = 0; pp < PTS / 8; pp++) {
        int pt = pp * 8 + wid;
        int n  = nbase + pt;

        const int* ip = g_idx + ((size_t)b * Nn + n) * Kn;
        int myid = (lane < Kn) ? ip[lane] : n;
#pragma unroll
        for (int r = 0; r < 18; r += 2) {
            int rr = r + (lane >> 4);
            int rowid = __shfl_sync(0xffffffffu, myid, rr & 31);
            if (rr >= Kn) rowid = n;
            if (rr < 17)
                ((float4*)(fw + rr * Cn))[lane & 15] =
                    ((const float4*)(xtb + (size_t)rowid * Cn))[lane & 15];
        }
        __syncwarp();

        float csv[4] = {0.f, 0.f, 0.f, 0.f};
        {
            const float* cen = fw + 16 * Cn;
#pragma unroll
            for (int c = 0; c < Cn; c++) {
                float e = cen[c];
                float4 wv = *(const float4*)(g_wd + c * On + o0);
                csv[0] += wv.x * e; csv[1] += wv.y * e;
                csv[2] += wv.z * e; csv[3] += wv.w * e;
            }
        }

        float mx[4], mn[4];
#pragma unroll 1
        for (int k = 0; k < Kn; k++) {
            const float4* fr = (const float4*)(fw + k * Cn);
            float a0 = 0.f, a1 = 0.f, a2 = 0.f, a3 = 0.f;
#pragma unroll
            for (int c4 = 0; c4 < Cn / 4; c4++) {
                float4 e = fr[c4];
                const float* wb = w1 + (c4 * 4) * On + o0;
                float4 w0 = *(const float4*)(wb);
                a0 += w0.x * e.x; a1 += w0.y * e.x; a2 += w0.z * e.x; a3 += w0.w * e.x;
                float4 wv1 = *(const float4*)(wb + On);
                a0 += wv1.x * e.y; a1 += wv1.y * e.y; a2 += wv1.z * e.y; a3 += wv1.w * e.y;
                float4 wv2 = *(const float4*)(wb + 2 * On);
                a0 += wv2.x * e.z; a1 += wv2.y * e.z; a2 += wv2.z * e.z; a3 += wv2.w * e.z;
                float4 wv3 = *(const float4*)(wb + 3 * On);
                a0 += wv3.x * e.w; a1 += wv3.y * e.w; a2 += wv3.z * e.w; a3 += wv3.w * e.w;
            }
            if (k == 0) {
                mx[0] = a0; mx[1] = a1; mx[2] = a2; mx[3] = a3;
                mn[0] = a0; mn[1] = a1; mn[2] = a2; mn[3] = a3;
            } else {
                mx[0] = fmaxf(mx[0], a0); mn[0] = fminf(mn[0], a0);
                mx[1] = fmaxf(mx[1], a1); mn[1] = fminf(mn[1], a1);
                mx[2] = fmaxf(mx[2], a2); mn[2] = fminf(mn[2], a2);
                mx[3] = fmaxf(mx[3], a3); mn[3] = fminf(mn[3], a3);
            }
        }

        float* od = outs + pt * 132 + o0;
#pragma unroll
        for (int r = 0; r < 4; r++) {
            float sc = ssc[o0 + r];
            float bi = sbi[o0 + r];
            float base = (sc > 0.f ? mx[r] : mn[r]) + csv[r];
            float yv = fmaf(sc, base, bi);
            yv = yv > 0.f ? yv : NEGf * yv;
            od[r] = yv;
        }
        __syncwarp();
    }

    __syncthreads();
    {
        int o = tid >> 1, h = tid & 1;
        float* dst = out + ((size_t)(b * On + o)) * Nn + nbase + h * 16;
#pragma unroll
        for (int i4 = 0; i4 < 4; i4++) {
            float4 vv;
            vv.x = outs[(h * 16 + i4 * 4 + 0) * 132 + o];
            vv.y = outs[(h * 16 + i4 * 4 + 1) * 132 + o];
            vv.z = outs[(h * 16 + i4 * 4 + 2) * 132 + o];
            vv.w = outs[(h * 16 + i4 * 4 + 3) * 132 + o];
            *(float4*)(dst + i4 * 4) = vv;
        }
    }
}

// ---------------- launch ----------------
extern "C" void kernel_launch(void* const* d_in, const int* in_sizes, int n_in,
                              void* d_out, int out_size) {
    const float* x       = (const float*)d_in[0];
    const float* W       = (const float*)d_in[1];
    const float* gamma   = (const float*)d_in[2];
    const float* beta    = (const float*)d_in[3];
    const float* bn_mean = (const float*)d_in[4];
    const float* bn_var  = (const float*)d_in[5];
    float* out = (float*)d_out;

    const size_t knn_smem  = KNN_SMEM_FLOATS * sizeof(float);
    const size_t edge_smem = EDGE_SMEM_FLOATS * sizeof(float);
    cudaFuncSetAttribute(knn_kernel, cudaFuncAttributeMaxDynamicSharedMemorySize,
                         (int)knn_smem);
    cudaFuncSetAttribute(edge_kernel, cudaFuncAttributeMaxDynamicSharedMemorySize,
                         (int)edge_smem);

    prep_kernel<<<1, On>>>(W, gamma, beta, bn_mean, bn_var);
    transpose_kernel<<<dim3(Nn / 32, Bn), dim3(32, 8)>>>(x);
    norm_kernel<<<dim3(Nn / 256, Bn), 256>>>(x);
    knn_kernel<<<Bn * (Nn / QT), 256, knn_smem>>>();
    edge_kernel<<<(Bn * Nn) / PTS, 256, edge_smem>>>(out);
}

// round 7
// speedup vs baseline: 1.2088x; 1.2052x over previous
#include <cuda_runtime.h>
#include <cstdint>

#define Bn 4
#define Cn 64
#define Nn 16384
#define On 128
#define Kn 16
#define EPSf 1e-5f
#define NEGf 0.2f
#define FLT_NEG (-3.402823466e38f)
#define FLT_POS (3.402823466e38f)
#define PTS 32

// -------- scratch (__device__ globals) --------
__device__ __align__(16) float g_xt[Bn * Nn * Cn];   // (b,n,c) fp32
__device__ __align__(16) float g_xn[Bn * Nn];        // 0.5 * |x|^2
__device__ __align__(16) int   g_idx[Bn * Nn * Kn];
__device__ __align__(16) float g_w1[Cn * On];
__device__ __align__(16) float g_wd[Cn * On];
__device__ float g_scale[On];
__device__ float g_bias[On];

// ---------------- PTX helpers ----------------
__device__ __forceinline__ uint32_t smem_u32(const void* p) {
    uint32_t a;
    asm("{ .reg .u64 t; cvta.to.shared.u64 t, %1; cvt.u32.u64 %0, t; }" : "=r"(a) : "l"(p));
    return a;
}
__device__ __forceinline__ uint32_t f2tf(float x) {
    uint32_t r; asm("cvt.rna.tf32.f32 %0, %1;" : "=r"(r) : "f"(x)); return r;
}
__device__ __forceinline__ void mma_tf32(float* d, const uint32_t* a, const uint32_t* b) {
    asm volatile("mma.sync.aligned.m16n8k8.row.col.f32.tf32.tf32.f32 "
        "{%0,%1,%2,%3}, {%4,%5,%6,%7}, {%8,%9}, {%0,%1,%2,%3};"
        : "+f"(d[0]), "+f"(d[1]), "+f"(d[2]), "+f"(d[3])
        : "r"(a[0]), "r"(a[1]), "r"(a[2]), "r"(a[3]), "r"(b[0]), "r"(b[1]));
}
#define CP_ASYNC16(dst, src) \
    asm volatile("cp.async.cg.shared.global [%0], [%1], 16;" :: "r"(dst), "l"(src))
#define CP_COMMIT() asm volatile("cp.async.commit_group;" ::: "memory")
#define CP_WAIT1()  asm volatile("cp.async.wait_group 1;" ::: "memory")

__device__ __forceinline__ void fma2(unsigned long long& d, unsigned long long a, unsigned long long b) {
    asm("fma.rn.f32x2 %0, %1, %2, %0;" : "+l"(d) : "l"(a), "l"(b));
}
__device__ __forceinline__ unsigned long long pack2(float v) {
    unsigned long long r; asm("mov.b64 %0, {%1, %1};" : "=l"(r) : "f"(v)); return r;
}
__device__ __forceinline__ void unpack2(unsigned long long v, float& lo, float& hi) {
    asm("mov.b64 {%0, %1}, %2;" : "=f"(lo), "=f"(hi) : "l"(v));
}

// ---------------- weight / BN prep ----------------
__global__ void prep_kernel(const float* __restrict__ W,
                            const float* __restrict__ gamma,
                            const float* __restrict__ beta,
                            const float* __restrict__ bn_mean,
                            const float* __restrict__ bn_var) {
    int o = threadIdx.x;
    float sc = gamma[o] * rsqrtf(bn_var[o] + EPSf);
    g_scale[o] = sc;
    g_bias[o]  = beta[o] - bn_mean[o] * sc;
    for (int c = 0; c < Cn; c++) {
        float w1 = W[o * (2 * Cn) + c];
        float w2 = W[o * (2 * Cn) + Cn + c];
        g_w1[c * On + o] = w1;
        g_wd[c * On + o] = w2 - w1;
    }
}

// ---------------- transpose x (B,C,N) -> xt (B,N,C) ----------------
__global__ void transpose_kernel(const float* __restrict__ x) {
    __shared__ float s[32][65];
    int b  = blockIdx.y;
    int nb = blockIdx.x * 32;
    int tx = threadIdx.x, ty = threadIdx.y;
    const float* xb = x + (size_t)b * Cn * Nn;
#pragma unroll
    for (int i = 0; i < 8; i++) {
        int c = ty * 8 + i;
        s[tx][c] = xb[(size_t)c * Nn + nb + tx];
    }
    __syncthreads();
    int t = ty * 32 + tx;
    int r = t >> 3;
    int c0 = (t & 7) * 8;
    float* dst = g_xt + ((size_t)b * Nn + nb + r) * Cn + c0;
#pragma unroll
    for (int i = 0; i < 8; i++) dst[i] = s[r][c0 + i];
}

// ---------------- half squared norms ----------------
__global__ void norm_kernel(const float* __restrict__ x) {
    int n = blockIdx.x * blockDim.x + threadIdx.x;
    int b = blockIdx.y;
    const float* xb = x + (size_t)b * Cn * Nn + n;
    float s = 0.f;
#pragma unroll
    for (int c = 0; c < Cn; c++) { float v = xb[(size_t)c * Nn]; s += v * v; }
    g_xn[b * Nn + n] = 0.5f * s;
}

// ---------------- KNN via mma.sync tf32 (3xTF32) ----------------
// smem floats: AS[128][68] | BS[2][128][68] | NS[2][128] | S[128][SSTR]
#define SSTR 129
#define AS_OFF 0
#define BS_OFF (128 * 68)
#define NS_OFF (BS_OFF + 2 * 128 * 68)
#define S_OFF  (NS_OFF + 2 * 128)
#define KNN_SMEM_FLOATS (S_OFF + 128 * SSTR)

__device__ __forceinline__ void prefetch_tile(uint32_t bs_u32, uint32_t ns_u32,
                                              const float* __restrict__ xt,
                                              const float* __restrict__ xn,
                                              int rowbase, int tid) {
#pragma unroll
    for (int i = 0; i < 8; i++) {
        int idx = tid + i * 256;                     // 0..2047
        int r = idx >> 4, k4 = idx & 15;
        CP_ASYNC16(bs_u32 + (uint32_t)(r * 272 + k4 * 16),
                   xt + (size_t)(rowbase + r) * Cn + k4 * 4);
    }
    if (tid < 32)
        CP_ASYNC16(ns_u32 + (uint32_t)tid * 16, xn + rowbase + tid * 4);
}

__global__ __launch_bounds__(256, 1) void knn_kernel() {
    extern __shared__ __align__(16) float sh[];
    float* AS = sh + AS_OFF;
    float* BS = sh + BS_OFF;
    float* NS = sh + NS_OFF;
    float* S  = sh + S_OFF;
    const uint32_t as_u = smem_u32(AS);
    const uint32_t bs_u = smem_u32(BS);
    const uint32_t ns_u = smem_u32(NS);

    const int tid = threadIdx.x;
    const int wid = tid >> 5, lane = tid & 31;
    const int g = lane >> 2, t4 = lane & 3;
    const int warp_m = wid >> 1, warp_n = wid & 1;
    const int m0 = warp_m * 32, n0 = warp_n * 64;

    const int b = blockIdx.x >> 7;
    const int qbase = (blockIdx.x & 127) << 7;
    const float* xt = g_xt + (size_t)b * Nn * Cn;
    const float* xn = g_xn + (size_t)b * Nn;

    // preload A (queries) + tiles 0,1
#pragma unroll
    for (int i = 0; i < 8; i++) {
        int idx = tid + i * 256;
        int r = idx >> 4, k4 = idx & 15;
        CP_ASYNC16(as_u + (uint32_t)(r * 272 + k4 * 16),
                   xt + (size_t)(qbase + r) * Cn + k4 * 4);
    }
    prefetch_tile(bs_u, ns_u, xt, xn, 0, tid);
    CP_COMMIT();
    prefetch_tile(bs_u + 128 * 272, ns_u + 512, xt, xn, 128, tid);
    CP_COMMIT();

    // selection state
    float vtop[Kn]; int itop[Kn];
#pragma unroll
    for (int u = 0; u < Kn; u++) { vtop[u] = FLT_NEG; itop[u] = 0; }
    float vmin = FLT_NEG; int smin = 0;
    const int selq = tid & 127;
    const int selhalf = tid >> 7;
    const int qi = qbase + selq;
    const float* Srow = S + selq * SSTR + selhalf * 64;

    // per-warp A row pointers
    const float* A0 = AS + (m0 + g) * 68;        // mt=0 row g
    const float* A1 = AS + (m0 + g + 8) * 68;
    const float* A2 = AS + (m0 + 16 + g) * 68;   // mt=1
    const float* A3 = AS + (m0 + 16 + g + 8) * 68;

#pragma unroll 1
    for (int t = 0; t < Nn / 128; t++) {
        CP_WAIT1();
        __syncthreads();

        const float* Bbuf = BS + (t & 1) * (128 * 68);
        const float* nsb  = NS + (t & 1) * 128;

        float acc[2][8][4];
#pragma unroll
        for (int mt = 0; mt < 2; mt++)
#pragma unroll
            for (int nt = 0; nt < 8; nt++)
#pragma unroll
                for (int r = 0; r < 4; r++) acc[mt][nt][r] = 0.f;

#pragma unroll 1
        for (int k8 = 0; k8 < 8; k8++) {
            const int kc = k8 * 8;
            uint32_t ah[2][4], al[2][4];
            {
                float a0 = A0[kc + t4],     a1 = A1[kc + t4];
                float a2 = A0[kc + t4 + 4], a3 = A1[kc + t4 + 4];
                ah[0][0] = f2tf(a0); al[0][0] = f2tf(a0 - __uint_as_float(ah[0][0]));
                ah[0][1] = f2tf(a1); al[0][1] = f2tf(a1 - __uint_as_float(ah[0][1]));
                ah[0][2] = f2tf(a2); al[0][2] = f2tf(a2 - __uint_as_float(ah[0][2]));
                ah[0][3] = f2tf(a3); al[0][3] = f2tf(a3 - __uint_as_float(ah[0][3]));
                float c0 = A2[kc + t4],     c1 = A3[kc + t4];
                float c2 = A2[kc + t4 + 4], c3 = A3[kc + t4 + 4];
                ah[1][0] = f2tf(c0); al[1][0] = f2tf(c0 - __uint_as_float(ah[1][0]));
                ah[1][1] = f2tf(c1); al[1][1] = f2tf(c1 - __uint_as_float(ah[1][1]));
                ah[1][2] = f2tf(c2); al[1][2] = f2tf(c2 - __uint_as_float(ah[1][2]));
                ah[1][3] = f2tf(c3); al[1][3] = f2tf(c3 - __uint_as_float(ah[1][3]));
            }
#pragma unroll
            for (int nt = 0; nt < 8; nt++) {
                const float* Brow = Bbuf + (n0 + nt * 8 + g) * 68 + kc;
                float b0 = Brow[t4], b1 = Brow[t4 + 4];
                uint32_t bh[2], bl[2];
                bh[0] = f2tf(b0); bl[0] = f2tf(b0 - __uint_as_float(bh[0]));
                bh[1] = f2tf(b1); bl[1] = f2tf(b1 - __uint_as_float(bh[1]));
#pragma unroll
                for (int mt = 0; mt < 2; mt++) {
                    mma_tf32(acc[mt][nt], ah[mt], bh);
                    mma_tf32(acc[mt][nt], al[mt], bh);
                    mma_tf32(acc[mt][nt], ah[mt], bl);
                }
            }
        }

        // spill scores - norms to S
#pragma unroll
        for (int nt = 0; nt < 8; nt++) {
            int c0 = n0 + nt * 8 + 2 * t4;
            float nv0 = nsb[c0], nv1 = nsb[c0 + 1];
#pragma unroll
            for (int mt = 0; mt < 2; mt++) {
                int r0 = m0 + mt * 16 + g;
                S[r0 * SSTR + c0]           = acc[mt][nt][0] - nv0;
                S[r0 * SSTR + c0 + 1]       = acc[mt][nt][1] - nv1;
                S[(r0 + 8) * SSTR + c0]     = acc[mt][nt][2] - nv0;
                S[(r0 + 8) * SSTR + c0 + 1] = acc[mt][nt][3] - nv1;
            }
        }
        __syncthreads();

        if (t + 2 < Nn / 128)
            prefetch_tile(bs_u + (uint32_t)(t & 1) * (128 * 272),
                          ns_u + (uint32_t)(t & 1) * 512, xt, xn, (t + 2) * 128, tid);
        CP_COMMIT();

        // selection: 2 threads per query, 64 cols each
        const int jg0 = t * 128 + selhalf * 64;
#pragma unroll 4
        for (int c = 0; c < 64; c++) {
            float sv = Srow[c];
            if (sv > vmin) {
                int jg = jg0 + c;
                if (jg != qi) {
                    vtop[smin] = sv; itop[smin] = jg;
                    float m = vtop[0]; int sm = 0;
#pragma unroll
                    for (int u = 1; u < Kn; u++)
                        if (vtop[u] < m) { m = vtop[u]; sm = u; }
                    vmin = m; smin = sm;
                }
            }
        }
    }

    // merge halves (reuse S)
    __syncthreads();
    float* mv = S;
    int*   mi = (int*)(S + 128 * Kn);
    if (selhalf == 1) {
#pragma unroll
        for (int u = 0; u < Kn; u++) {
            mv[selq * Kn + u] = vtop[u];
            mi[selq * Kn + u] = itop[u];
        }
    }
    __syncthreads();
    if (selhalf == 0) {
#pragma unroll
        for (int u = 0; u < Kn; u++) {
            float sv = mv[selq * Kn + u];
            if (sv > vmin) {
                vtop[smin] = sv; itop[smin] = mi[selq * Kn + u];
                float m = vtop[0]; int sm = 0;
#pragma unroll
                for (int w = 1; w < Kn; w++)
                    if (vtop[w] < m) { m = vtop[w]; sm = w; }
                vmin = m; smin = sm;
            }
        }
        int* op = g_idx + ((size_t)b * Nn + qi) * Kn;
#pragma unroll
        for (int u = 0; u < Kn; u++) op[u] = itop[u];
    }
}

// ---------------- edge conv + BN + lrelu + max over k ----------------
#define EDGE_SMEM_FLOATS (Cn*On + 8*17*Cn + PTS*132 + 2*On)

__global__ __launch_bounds__(256, 2) void edge_kernel(float* __restrict__ out) {
    extern __shared__ float sm[];
    float* w1   = sm;
    float* feat = w1 + Cn * On;
    float* outs = feat + 8 * 17 * Cn;
    float* ssc  = outs + PTS * 132;
    float* sbi  = ssc + On;

    int tid = threadIdx.x, wid = tid >> 5, lane = tid & 31;

    for (int i = tid; i < Cn * On; i += 256) w1[i] = g_w1[i];
    if (tid < On) { ssc[tid] = g_scale[tid]; sbi[tid] = g_bias[tid]; }
    __syncthreads();

    int gp    = blockIdx.x * PTS;
    int b     = gp / Nn;
    int nbase = gp % Nn;
    const float* xtb = g_xt + (size_t)b * Nn * Cn;
    float* fw = feat + wid * 17 * Cn;
    int o0 = lane << 2;

#pragma unroll 1
    for (int pp = 0; pp < PTS / 8; pp++) {
        int pt = pp * 8 + wid;
        int n  = nbase + pt;

        const int* ip = g_idx + ((size_t)b * Nn + n) * Kn;
        int myid = (lane < Kn) ? ip[lane] : n;
#pragma unroll
        for (int r = 0; r < 18; r += 2) {
            int rr = r + (lane >> 4);
            int rowid = __shfl_sync(0xffffffffu, myid, rr & 31);
            if (rr >= Kn) rowid = n;
            if (rr < 17)
                ((float4*)(fw + rr * Cn))[lane & 15] =
                    ((const float4*)(xtb + (size_t)rowid * Cn))[lane & 15];
        }
        __syncwarp();

        float csv[4] = {0.f, 0.f, 0.f, 0.f};
        {
            const float* cen = fw + 16 * Cn;
#pragma unroll
            for (int c = 0; c < Cn; c++) {
                float e = cen[c];
                float4 wv = *(const float4*)(g_wd + c * On + o0);
                csv[0] += wv.x * e; csv[1] += wv.y * e;
                csv[2] += wv.z * e; csv[3] += wv.w * e;
            }
        }

        float mx[4] = {FLT_NEG, FLT_NEG, FLT_NEG, FLT_NEG};
        float mn[4] = {FLT_POS, FLT_POS, FLT_POS, FLT_POS};

#pragma unroll 1
        for (int k0 = 0; k0 < Kn; k0 += 4) {
            unsigned long long acc2[4][2];
#pragma unroll
            for (int j = 0; j < 4; j++) { acc2[j][0] = 0ull; acc2[j][1] = 0ull; }
            const float4* f0 = (const float4*)(fw + (k0 + 0) * Cn);
            const float4* f1 = (const float4*)(fw + (k0 + 1) * Cn);
            const float4* f2 = (const float4*)(fw + (k0 + 2) * Cn);
            const float4* f3 = (const float4*)(fw + (k0 + 3) * Cn);
#pragma unroll
            for (int c4 = 0; c4 < Cn / 4; c4++) {
                float4 e0 = f0[c4], e1 = f1[c4], e2 = f2[c4], e3 = f3[c4];
#pragma unroll
                for (int cc = 0; cc < 4; cc++) {
                    const float* wb = w1 + (c4 * 4 + cc) * On + o0;
                    unsigned long long wA = *(const unsigned long long*)wb;
                    unsigned long long wB = *(const unsigned long long*)(wb + 2);
                    float v0 = (cc == 0) ? e0.x : (cc == 1) ? e0.y : (cc == 2) ? e0.z : e0.w;
                    float v1 = (cc == 0) ? e1.x : (cc == 1) ? e1.y : (cc == 2) ? e1.z : e1.w;
                    float v2 = (cc == 0) ? e2.x : (cc == 1) ? e2.y : (cc == 2) ? e2.z : e2.w;
                    float v3 = (cc == 0) ? e3.x : (cc == 1) ? e3.y : (cc == 2) ? e3.z : e3.w;
                    unsigned long long p0 = pack2(v0), p1 = pack2(v1),
                                       p2 = pack2(v2), p3 = pack2(v3);
                    fma2(acc2[0][0], p0, wA); fma2(acc2[0][1], p0, wB);
                    fma2(acc2[1][0], p1, wA); fma2(acc2[1][1], p1, wB);
                    fma2(acc2[2][0], p2, wA); fma2(acc2[2][1], p2, wB);
                    fma2(acc2[3][0], p3, wA); fma2(acc2[3][1], p3, wB);
                }
            }
#pragma unroll
            for (int j = 0; j < 4; j++) {
                float a0, a1, a2, a3;
                unpack2(acc2[j][0], a0, a1);
                unpack2(acc2[j][1], a2, a3);
                mx[0] = fmaxf(mx[0], a0); mn[0] = fminf(mn[0], a0);
                mx[1] = fmaxf(mx[1], a1); mn[1] = fminf(mn[1], a1);
                mx[2] = fmaxf(mx[2], a2); mn[2] = fminf(mn[2], a2);
                mx[3] = fmaxf(mx[3], a3); mn[3] = fminf(mn[3], a3);
            }
        }

        float* od = outs + pt * 132 + o0;
#pragma unroll
        for (int r = 0; r < 4; r++) {
            float sc = ssc[o0 + r];
            float bi = sbi[o0 + r];
            float base = (sc > 0.f ? mx[r] : mn[r]) + csv[r];
            float yv = fmaf(sc, base, bi);
            yv = yv > 0.f ? yv : NEGf * yv;
            od[r] = yv;
        }
        __syncwarp();
    }

    __syncthreads();
    {
        int o = tid >> 1, h = tid & 1;
        float* dst = out + ((size_t)(b * On + o)) * Nn + nbase + h * 16;
#pragma unroll
        for (int i4 = 0; i4 < 4; i4++) {
            float4 vv;
            vv.x = outs[(h * 16 + i4 * 4 + 0) * 132 + o];
            vv.y = outs[(h * 16 + i4 * 4 + 1) * 132 + o];
            vv.z = outs[(h * 16 + i4 * 4 + 2) * 132 + o];
            vv.w = outs[(h * 16 + i4 * 4 + 3) * 132 + o];
            *(float4*)(dst + i4 * 4) = vv;
        }
    }
}

// ---------------- launch ----------------
extern "C" void kernel_launch(void* const* d_in, const int* in_sizes, int n_in,
                              void* d_out, int out_size) {
    const float* x       = (const float*)d_in[0];
    const float* W       = (const float*)d_in[1];
    const float* gamma   = (const float*)d_in[2];
    const float* beta    = (const float*)d_in[3];
    const float* bn_mean = (const float*)d_in[4];
    const float* bn_var  = (const float*)d_in[5];
    float* out = (float*)d_out;

    const size_t knn_smem  = KNN_SMEM_FLOATS * sizeof(float);
    const size_t edge_smem = EDGE_SMEM_FLOATS * sizeof(float);
    cudaFuncSetAttribute(knn_kernel, cudaFuncAttributeMaxDynamicSharedMemorySize,
                         (int)knn_smem);
    cudaFuncSetAttribute(edge_kernel, cudaFuncAttributeMaxDynamicSharedMemorySize,
                         (int)edge_smem);

    prep_kernel<<<1, On>>>(W, gamma, beta, bn_mean, bn_var);
    transpose_kernel<<<dim3(Nn / 32, Bn), dim3(32, 8)>>>(x);
    norm_kernel<<<dim3(Nn / 256, Bn), 256>>>(x);
    knn_kernel<<<Bn * (Nn / 128), 256, knn_smem>>>();
    edge_kernel<<<(Bn * Nn) / PTS, 256, edge_smem>>>(out);
}

// round 11
// speedup vs baseline: 1.2650x; 1.0465x over previous
#include <cuda_runtime.h>
#include <cstdint>

#define Bn 4
#define Cn 64
#define Nn 16384
#define On 128
#define Kn 16
#define EPSf 1e-5f
#define NEGf 0.2f
#define FLT_NEG (-3.402823466e38f)
#define FLT_POS (3.402823466e38f)
#define PTS 32
#define CT 64                    // candidates per tile (smaller -> 2 CTAs/SM)

// -------- scratch (__device__ globals) --------
__device__ __align__(16) float g_xt[Bn * Nn * Cn];   // (b,n,c) fp32
__device__ __align__(16) float g_xn[Bn * Nn];        // 0.5 * |x|^2
__device__ __align__(16) int   g_idx[Bn * Nn * Kn];
__device__ __align__(16) float g_w1[Cn * On];
__device__ __align__(16) float g_wd[Cn * On];
__device__ float g_scale[On];
__device__ float g_bias[On];

// ---------------- PTX helpers ----------------
__device__ __forceinline__ uint32_t smem_u32(const void* p) {
    uint32_t a;
    asm("{ .reg .u64 t; cvta.to.shared.u64 t, %1; cvt.u32.u64 %0, t; }" : "=r"(a) : "l"(p));
    return a;
}
__device__ __forceinline__ uint32_t f2tf(float x) {
    uint32_t r; asm("cvt.rna.tf32.f32 %0, %1;" : "=r"(r) : "f"(x)); return r;
}
__device__ __forceinline__ void mma_tf32(float* d, const uint32_t* a, const uint32_t* b) {
    asm volatile("mma.sync.aligned.m16n8k8.row.col.f32.tf32.tf32.f32 "
        "{%0,%1,%2,%3}, {%4,%5,%6,%7}, {%8,%9}, {%0,%1,%2,%3};"
        : "+f"(d[0]), "+f"(d[1]), "+f"(d[2]), "+f"(d[3])
        : "r"(a[0]), "r"(a[1]), "r"(a[2]), "r"(a[3]), "r"(b[0]), "r"(b[1]));
}
#define CP_ASYNC16(dst, src) \
    asm volatile("cp.async.cg.shared.global [%0], [%1], 16;" :: "r"(dst), "l"(src))
#define CP_COMMIT() asm volatile("cp.async.commit_group;" ::: "memory")
#define CP_WAIT1()  asm volatile("cp.async.wait_group 1;" ::: "memory")

__device__ __forceinline__ void fma2(unsigned long long& d, unsigned long long a, unsigned long long b) {
    asm("fma.rn.f32x2 %0, %1, %2, %0;" : "+l"(d) : "l"(a), "l"(b));
}
__device__ __forceinline__ unsigned long long pack2(float v) {
    unsigned long long r; asm("mov.b64 %0, {%1, %1};" : "=l"(r) : "f"(v)); return r;
}
__device__ __forceinline__ void unpack2(unsigned long long v, float& lo, float& hi) {
    asm("mov.b64 {%0, %1}, %2;" : "=f"(lo), "=f"(hi) : "l"(v));
}

// ---------------- weight / BN prep ----------------
__global__ void prep_kernel(const float* __restrict__ W,
                            const float* __restrict__ gamma,
                            const float* __restrict__ beta,
                            const float* __restrict__ bn_mean,
                            const float* __restrict__ bn_var) {
    int o = threadIdx.x;
    float sc = gamma[o] * rsqrtf(bn_var[o] + EPSf);
    g_scale[o] = sc;
    g_bias[o]  = beta[o] - bn_mean[o] * sc;
    for (int c = 0; c < Cn; c++) {
        float w1 = W[o * (2 * Cn) + c];
        float w2 = W[o * (2 * Cn) + Cn + c];
        g_w1[c * On + o] = w1;
        g_wd[c * On + o] = w2 - w1;
    }
}

// ---------------- transpose x (B,C,N) -> xt (B,N,C) ----------------
__global__ void transpose_kernel(const float* __restrict__ x) {
    __shared__ float s[32][65];
    int b  = blockIdx.y;
    int nb = blockIdx.x * 32;
    int tx = threadIdx.x, ty = threadIdx.y;
    const float* xb = x + (size_t)b * Cn * Nn;
#pragma unroll
    for (int i = 0; i < 8; i++) {
        int c = ty * 8 + i;
        s[tx][c] = xb[(size_t)c * Nn + nb + tx];
    }
    __syncthreads();
    int t = ty * 32 + tx;
    int r = t >> 3;
    int c0 = (t & 7) * 8;
    float* dst = g_xt + ((size_t)b * Nn + nb + r) * Cn + c0;
#pragma unroll
    for (int i = 0; i < 8; i++) dst[i] = s[r][c0 + i];
}

// ---------------- half squared norms ----------------
__global__ void norm_kernel(const float* __restrict__ x) {
    int n = blockIdx.x * blockDim.x + threadIdx.x;
    int b = blockIdx.y;
    const float* xb = x + (size_t)b * Cn * Nn + n;
    float s = 0.f;
#pragma unroll
    for (int c = 0; c < Cn; c++) { float v = xb[(size_t)c * Nn]; s += v * v; }
    g_xn[b * Nn + n] = 0.5f * s;
}

// ---------------- KNN via mma.sync tf32 (3xTF32), CT=64, 2 CTAs/SM ----
// smem floats: AS[128][68] | BS[2][64][68] | NS[4][64] | S[128][65]
#define AS_OFF 0
#define BS_OFF (128 * 68)                    // 8704
#define BS_BUF (CT * 68)                     // 4352 floats per buffer
#define NS_OFF (BS_OFF + 2 * BS_BUF)         // 17408
#define S_OFF  (NS_OFF + 4 * CT)             // 17664
#define KNN_SMEM_FLOATS (S_OFF + 128 * 65)   // 25984 -> 103,936 B

__device__ __forceinline__ void prefetch_tile(uint32_t bs_u32, uint32_t ns_u32,
                                              const float* __restrict__ xt,
                                              const float* __restrict__ xn,
                                              int rowbase, int tid) {
#pragma unroll
    for (int i = 0; i < 4; i++) {
        int idx = tid + i * 256;                     // 0..1023 (64 rows x 16 f4)
        int r = idx >> 4, k4 = idx & 15;
        CP_ASYNC16(bs_u32 + (uint32_t)(r * 272 + k4 * 16),
                   xt + (size_t)(rowbase + r) * Cn + k4 * 4);
    }
    if (tid < 16)
        CP_ASYNC16(ns_u32 + (uint32_t)tid * 16, xn + rowbase + tid * 4);
}

__global__ __launch_bounds__(256, 2) void knn_kernel() {
    extern __shared__ __align__(16) float sh[];
    float* AS = sh + AS_OFF;
    float* BS = sh + BS_OFF;
    float* NS = sh + NS_OFF;
    float* S  = sh + S_OFF;
    const uint32_t as_u = smem_u32(AS);
    const uint32_t bs_u = smem_u32(BS);
    const uint32_t ns_u = smem_u32(NS);

    const int tid = threadIdx.x;
    const int wid = tid >> 5, lane = tid & 31;
    const int g = lane >> 2, t4 = lane & 3;
    const int warp_m = wid >> 1, warp_n = wid & 1;
    const int m0 = warp_m * 32, n0 = warp_n * 32;

    const int b = blockIdx.x >> 7;
    const int qbase = (blockIdx.x & 127) << 7;
    const float* xt = g_xt + (size_t)b * Nn * Cn;
    const float* xn = g_xn + (size_t)b * Nn;

    // preload A (128 queries) + candidate tiles 0,1
#pragma unroll
    for (int i = 0; i < 8; i++) {
        int idx = tid + i * 256;                     // 0..2047
        int r = idx >> 4, k4 = idx & 15;
        CP_ASYNC16(as_u + (uint32_t)(r * 272 + k4 * 16),
                   xt + (size_t)(qbase + r) * Cn + k4 * 4);
    }
    prefetch_tile(bs_u, ns_u, xt, xn, 0, tid);
    CP_COMMIT();
    prefetch_tile(bs_u + BS_BUF * 4, ns_u + CT * 4, xt, xn, CT, tid);
    CP_COMMIT();

    // selection state
    float vtop[Kn]; int itop[Kn];
#pragma unroll
    for (int u = 0; u < Kn; u++) { vtop[u] = FLT_NEG; itop[u] = 0; }
    float vmin = FLT_NEG; int smin = 0;
    const int selq = tid & 127;
    const int selhalf = tid >> 7;
    const int qi = qbase + selq;
    const float* Srow = S + selq * 65 + selhalf * 32;

    // per-warp A row pointers
    const float* A0 = AS + (m0 + g) * 68;        // mt=0 row g
    const float* A1 = AS + (m0 + g + 8) * 68;
    const float* A2 = AS + (m0 + 16 + g) * 68;   // mt=1
    const float* A3 = AS + (m0 + 16 + g + 8) * 68;

#pragma unroll 1
    for (int t = 0; t < Nn / CT; t++) {
        CP_WAIT1();
        __syncthreads();

        const float* Bbuf = BS + (t & 1) * BS_BUF;
        const float* nsb  = NS + (t & 3) * CT;       // 4-slot norm ring

        float acc[2][4][4];
#pragma unroll
        for (int mt = 0; mt < 2; mt++)
#pragma unroll
            for (int nt = 0; nt < 4; nt++)
#pragma unroll
                for (int r = 0; r < 4; r++) acc[mt][nt][r] = 0.f;

#pragma unroll 1
        for (int k8 = 0; k8 < 8; k8++) {
            const int kc = k8 * 8;
            uint32_t ah[2][4], al[2][4];
            {
                float a0 = A0[kc + t4],     a1 = A1[kc + t4];
                float a2 = A0[kc + t4 + 4], a3 = A1[kc + t4 + 4];
                ah[0][0] = f2tf(a0); al[0][0] = f2tf(a0 - __uint_as_float(ah[0][0]));
                ah[0][1] = f2tf(a1); al[0][1] = f2tf(a1 - __uint_as_float(ah[0][1]));
                ah[0][2] = f2tf(a2); al[0][2] = f2tf(a2 - __uint_as_float(ah[0][2]));
                ah[0][3] = f2tf(a3); al[0][3] = f2tf(a3 - __uint_as_float(ah[0][3]));
                float c0 = A2[kc + t4],     c1 = A3[kc + t4];
                float c2 = A2[kc + t4 + 4], c3 = A3[kc + t4 + 4];
                ah[1][0] = f2tf(c0); al[1][0] = f2tf(c0 - __uint_as_float(ah[1][0]));
                ah[1][1] = f2tf(c1); al[1][1] = f2tf(c1 - __uint_as_float(ah[1][1]));
                ah[1][2] = f2tf(c2); al[1][2] = f2tf(c2 - __uint_as_float(ah[1][2]));
                ah[1][3] = f2tf(c3); al[1][3] = f2tf(c3 - __uint_as_float(ah[1][3]));
            }
#pragma unroll
            for (int nt = 0; nt < 4; nt++) {
                const float* Brow = Bbuf + (n0 + nt * 8 + g) * 68 + kc;
                float b0 = Brow[t4], b1 = Brow[t4 + 4];
                uint32_t bh[2], bl[2];
                bh[0] = f2tf(b0); bl[0] = f2tf(b0 - __uint_as_float(bh[0]));
                bh[1] = f2tf(b1); bl[1] = f2tf(b1 - __uint_as_float(bh[1]));
#pragma unroll
                for (int mt = 0; mt < 2; mt++) {
                    mma_tf32(acc[mt][nt], ah[mt], bh);
                    mma_tf32(acc[mt][nt], al[mt], bh);
                    mma_tf32(acc[mt][nt], ah[mt], bl);
                }
            }
        }

        // spill scores - norms to S (cols 0..63)
#pragma unroll
        for (int nt = 0; nt < 4; nt++) {
            int c0 = n0 + nt * 8 + 2 * t4;
            float nv0 = nsb[c0], nv1 = nsb[c0 + 1];
#pragma unroll
            for (int mt = 0; mt < 2; mt++) {
                int r0 = m0 + mt * 16 + g;
                S[r0 * 65 + c0]           = acc[mt][nt][0] - nv0;
                S[r0 * 65 + c0 + 1]       = acc[mt][nt][1] - nv1;
                S[(r0 + 8) * 65 + c0]     = acc[mt][nt][2] - nv0;
                S[(r0 + 8) * 65 + c0 + 1] = acc[mt][nt][3] - nv1;
            }
        }
        __syncthreads();

        if (t + 2 < Nn / CT)
            prefetch_tile(bs_u + (uint32_t)(t & 1) * (BS_BUF * 4),
                          ns_u + (uint32_t)((t + 2) & 3) * (CT * 4),
                          xt, xn, (t + 2) * CT, tid);
        CP_COMMIT();

        // selection: 2 threads per query, 32 cols each
        const int jg0 = t * CT + selhalf * 32;
#pragma unroll 4
        for (int c = 0; c < 32; c++) {
            float sv = Srow[c];
            if (sv > vmin) {
                int jg = jg0 + c;
                if (jg != qi) {
                    vtop[smin] = sv; itop[smin] = jg;
                    float m = vtop[0]; int sm = 0;
#pragma unroll
                    for (int u = 1; u < Kn; u++)
                        if (vtop[u] < m) { m = vtop[u]; sm = u; }
                    vmin = m; smin = sm;
                }
            }
        }
    }

    // merge halves (reuse S)
    __syncthreads();
    float* mv = S;
    int*   mi = (int*)(S + 128 * Kn);
    if (selhalf == 1) {
#pragma unroll
        for (int u = 0; u < Kn; u++) {
            mv[selq * Kn + u] = vtop[u];
            mi[selq * Kn + u] = itop[u];
        }
    }
    __syncthreads();
    if (selhalf == 0) {
#pragma unroll
        for (int u = 0; u < Kn; u++) {
            float sv = mv[selq * Kn + u];
            if (sv > vmin) {
                vtop[smin] = sv; itop[smin] = mi[selq * Kn + u];
                float m = vtop[0]; int sm = 0;
#pragma unroll
                for (int w = 1; w < Kn; w++)
                    if (vtop[w] < m) { m = vtop[w]; sm = w; }
                vmin = m; smin = sm;
            }
        }
        int* op = g_idx + ((size_t)b * Nn + qi) * Kn;
#pragma unroll
        for (int u = 0; u < Kn; u++) op[u] = itop[u];
    }
}

// ---------------- edge conv + BN + lrelu + max over k ----------------
#define EDGE_SMEM_FLOATS (Cn*On + 8*17*Cn + PTS*132 + 2*On)

__global__ __launch_bounds__(256, 2) void edge_kernel(float* __restrict__ out) {
    extern __shared__ float sm[];
    float* w1   = sm;
    float* feat = w1 + Cn * On;
    float* outs = feat + 8 * 17 * Cn;
    float* ssc  = outs + PTS * 132;
    float* sbi  = ssc + On;

    int tid = threadIdx.x, wid = tid >> 5, lane = tid & 31;

    for (int i = tid; i < Cn * On; i += 256) w1[i] = g_w1[i];
    if (tid < On) { ssc[tid] = g_scale[tid]; sbi[tid] = g_bias[tid]; }
    __syncthreads();

    int gp    = blockIdx.x * PTS;
    int b     = gp / Nn;
    int nbase = gp % Nn;
    const float* xtb = g_xt + (size_t)b * Nn * Cn;
    float* fw = feat + wid * 17 * Cn;
    int o0 = lane << 2;

#pragma unroll 1
    for (int pp = 0; pp < PTS / 8; pp++) {
        int pt = pp * 8 + wid;
        int n  = nbase + pt;

        const int* ip = g_idx + ((size_t)b * Nn + n) * Kn;
        int myid = (lane < Kn) ? ip[lane] : n;
#pragma unroll
        for (int r = 0; r < 18; r += 2) {
            int rr = r + (lane >> 4);
            int rowid = __shfl_sync(0xffffffffu, myid, rr & 31);
            if (rr >= Kn) rowid = n;
            if (rr < 17)
                ((float4*)(fw + rr * Cn))[lane & 15] =
                    ((const float4*)(xtb + (size_t)rowid * Cn))[lane & 15];
        }
        __syncwarp();

        float csv[4] = {0.f, 0.f, 0.f, 0.f};
        {
            const float* cen = fw + 16 * Cn;
#pragma unroll
            for (int c = 0; c < Cn; c++) {
                float e = cen[c];
                float4 wv = *(const float4*)(g_wd + c * On + o0);
                csv[0] += wv.x * e; csv[1] += wv.y * e;
                csv[2] += wv.z * e; csv[3] += wv.w * e;
            }
        }

        float mx[4] = {FLT_NEG, FLT_NEG, FLT_NEG, FLT_NEG};
        float mn[4] = {FLT_POS, FLT_POS, FLT_POS, FLT_POS};

#pragma unroll 1
        for (int k0 = 0; k0 < Kn; k0 += 4) {
            unsigned long long acc2[4][2];
#pragma unroll
            for (int j = 0; j < 4; j++) { acc2[j][0] = 0ull; acc2[j][1] = 0ull; }
            const float4* f0 = (const float4*)(fw + (k0 + 0) * Cn);
            const float4* f1 = (const float4*)(fw + (k0 + 1) * Cn);
            const float4* f2 = (const float4*)(fw + (k0 + 2) * Cn);
            const float4* f3 = (const float4*)(fw + (k0 + 3) * Cn);
#pragma unroll
            for (int c4 = 0; c4 < Cn / 4; c4++) {
                float4 e0 = f0[c4], e1 = f1[c4], e2 = f2[c4], e3 = f3[c4];
#pragma unroll
                for (int cc = 0; cc < 4; cc++) {
                    const float* wb = w1 + (c4 * 4 + cc) * On + o0;
                    unsigned long long wA = *(const unsigned long long*)wb;
                    unsigned long long wB = *(const unsigned long long*)(wb + 2);
                    float v0 = (cc == 0) ? e0.x : (cc == 1) ? e0.y : (cc == 2) ? e0.z : e0.w;
                    float v1 = (cc == 0) ? e1.x : (cc == 1) ? e1.y : (cc == 2) ? e1.z : e1.w;
                    float v2 = (cc == 0) ? e2.x : (cc == 1) ? e2.y : (cc == 2) ? e2.z : e2.w;
                    float v3 = (cc == 0) ? e3.x : (cc == 1) ? e3.y : (cc == 2) ? e3.z : e3.w;
                    unsigned long long p0 = pack2(v0), p1 = pack2(v1),
                                       p2 = pack2(v2), p3 = pack2(v3);
                    fma2(acc2[0][0], p0, wA); fma2(acc2[0][1], p0, wB);
                    fma2(acc2[1][0], p1, wA); fma2(acc2[1][1], p1, wB);
                    fma2(acc2[2][0], p2, wA); fma2(acc2[2][1], p2, wB);
                    fma2(acc2[3][0], p3, wA); fma2(acc2[3][1], p3, wB);
                }
            }
#pragma unroll
            for (int j = 0; j < 4; j++) {
                float a0, a1, a2, a3;
                unpack2(acc2[j][0], a0, a1);
                unpack2(acc2[j][1], a2, a3);
                mx[0] = fmaxf(mx[0], a0); mn[0] = fminf(mn[0], a0);
                mx[1] = fmaxf(mx[1], a1); mn[1] = fminf(mn[1], a1);
                mx[2] = fmaxf(mx[2], a2); mn[2] = fminf(mn[2], a2);
                mx[3] = fmaxf(mx[3], a3); mn[3] = fminf(mn[3], a3);
            }
        }

        float* od = outs + pt * 132 + o0;
#pragma unroll
        for (int r = 0; r < 4; r++) {
            float sc = ssc[o0 + r];
            float bi = sbi[o0 + r];
            float base = (sc > 0.f ? mx[r] : mn[r]) + csv[r];
            float yv = fmaf(sc, base, bi);
            yv = yv > 0.f ? yv : NEGf * yv;
            od[r] = yv;
        }
        __syncwarp();
    }

    __syncthreads();
    {
        int o = tid >> 1, h = tid & 1;
        float* dst = out + ((size_t)(b * On + o)) * Nn + nbase + h * 16;
#pragma unroll
        for (int i4 = 0; i4 < 4; i4++) {
            float4 vv;
            vv.x = outs[(h * 16 + i4 * 4 + 0) * 132 + o];
            vv.y = outs[(h * 16 + i4 * 4 + 1) * 132 + o];
            vv.z = outs[(h * 16 + i4 * 4 + 2) * 132 + o];
            vv.w = outs[(h * 16 + i4 * 4 + 3) * 132 + o];
            *(float4*)(dst + i4 * 4) = vv;
        }
    }
}

// ---------------- launch ----------------
extern "C" void kernel_launch(void* const* d_in, const int* in_sizes, int n_in,
                              void* d_out, int out_size) {
    const float* x       = (const float*)d_in[0];
    const float* W       = (const float*)d_in[1];
    const float* gamma   = (const float*)d_in[2];
    const float* beta    = (const float*)d_in[3];
    const float* bn_mean = (const float*)d_in[4];
    const float* bn_var  = (const float*)d_in[5];
    float* out = (float*)d_out;

    const size_t knn_smem  = KNN_SMEM_FLOATS * sizeof(float);
    const size_t edge_smem = EDGE_SMEM_FLOATS * sizeof(float);
    cudaFuncSetAttribute(knn_kernel, cudaFuncAttributeMaxDynamicSharedMemorySize,
                         (int)knn_smem);
    cudaFuncSetAttribute(edge_kernel, cudaFuncAttributeMaxDynamicSharedMemorySize,
                         (int)edge_smem);

    prep_kernel<<<1, On>>>(W, gamma, beta, bn_mean, bn_var);
    transpose_kernel<<<dim3(Nn / 32, Bn), dim3(32, 8)>>>(x);
    norm_kernel<<<dim3(Nn / 256, Bn), 256>>>(x);
    knn_kernel<<<Bn * (Nn / 128), 256, knn_smem>>>();
    edge_kernel<<<(Bn * Nn) / PTS, 256, edge_smem>>>(out);
}